// round 2
// baseline (speedup 1.0000x reference)
#include <cuda_runtime.h>
#include <cuda_bf16.h>
#include <math.h>

// Problem constants
#define BB 2
#define TT 2048
#define CC 1024
#define HH 16
#define HD 64
#define FHID 1536
#define MM (BB*TT)          // 4096
#define MSCALE 0.03125f     // 1/sqrt(1024)

// ------------------------------------------------------------------
// Scratch (static device globals — no allocation allowed)
// ------------------------------------------------------------------
__device__ float g_h   [MM*CC];
__device__ float g_ffnh[MM*FHID];
__device__ float g_xffn[MM*CC];
__device__ float g_qkv [MM*3*CC];
__device__ float g_y   [MM*CC];
__device__ float g_s   [MM*CC];
__device__ float g_mc  [MM*CC];
__device__ float g_cq  [MM*CC];
__device__ float g_ck  [MM*CC];
__device__ float g_cv  [MM*CC];
__device__ float g_cg  [MM*CC];
__device__ float g_vdyn[MM*CC];
__device__ float g_mo  [MM*CC];
__device__ float g_woh [MM*4*CC];

__device__ __forceinline__ float sigm(float x){ return 1.f/(1.f+__expf(-x)); }

// ------------------------------------------------------------------
// LayerNorm: one block per row of length 1024, 256 threads x 4 elems
// ------------------------------------------------------------------
__global__ void __launch_bounds__(256) ln_k(const float* __restrict__ x,
                                            const float* __restrict__ g,
                                            const float* __restrict__ b,
                                            float* __restrict__ out)
{
    __shared__ float sa[8], sb[8];
    int row = blockIdx.x, tid = threadIdx.x;
    const float* xr = x + (long)row*CC;
    float4 v = *(const float4*)(xr + tid*4);
    float s = v.x+v.y+v.z+v.w;
    float q = v.x*v.x + v.y*v.y + v.z*v.z + v.w*v.w;
    int lane = tid & 31, wid = tid >> 5;
    #pragma unroll
    for (int o=16;o;o>>=1){ s += __shfl_down_sync(~0u,s,o); q += __shfl_down_sync(~0u,q,o); }
    if (lane==0){ sa[wid]=s; sb[wid]=q; }
    __syncthreads();
    if (tid==0){ float ss=0,qq=0; for(int i=0;i<8;i++){ss+=sa[i];qq+=sb[i];} sa[0]=ss; sb[0]=qq; }
    __syncthreads();
    float mean = sa[0]*(1.f/CC);
    float var  = sb[0]*(1.f/CC) - mean*mean;
    float rstd = rsqrtf(var + 1e-5f);
    float4 gv = *(const float4*)(g + tid*4);
    float4 bv = *(const float4*)(b + tid*4);
    float4 o;
    o.x = (v.x-mean)*rstd*gv.x + bv.x;
    o.y = (v.y-mean)*rstd*gv.y + bv.y;
    o.z = (v.z-mean)*rstd*gv.z + bv.z;
    o.w = (v.w-mean)*rstd*gv.w + bv.w;
    *(float4*)(out + (long)row*CC + tid*4) = o;
}

// ------------------------------------------------------------------
// Row L2-normalize in place (ck)
// ------------------------------------------------------------------
__global__ void __launch_bounds__(256) knorm_k(float* __restrict__ ck)
{
    __shared__ float sb[8];
    int row = blockIdx.x, tid = threadIdx.x;
    float* xr = ck + (long)row*CC;
    float4 v = *(const float4*)(xr + tid*4);
    float q = v.x*v.x + v.y*v.y + v.z*v.z + v.w*v.w;
    int lane = tid & 31, wid = tid >> 5;
    #pragma unroll
    for (int o=16;o;o>>=1) q += __shfl_down_sync(~0u,q,o);
    if (lane==0) sb[wid]=q;
    __syncthreads();
    if (tid==0){ float qq=0; for(int i=0;i<8;i++) qq+=sb[i]; sb[0]=qq; }
    __syncthreads();
    float inv = 1.f / fmaxf(sqrtf(sb[0]), 1e-5f);
    v.x*=inv; v.y*=inv; v.z*=inv; v.w*=inv;
    *(float4*)(xr + tid*4) = v;
}

// ------------------------------------------------------------------
// RoPE on q and k inside qkv buffer (in-place)
// ------------------------------------------------------------------
__global__ void __launch_bounds__(256) rope_k(float* __restrict__ qkv,
                                              const float* __restrict__ cosT,
                                              const float* __restrict__ sinT)
{
    int idx = blockIdx.x*blockDim.x + threadIdx.x;   // B*T*H*32 = 2^21
    if (idx >= BB*TT*HH*32) return;
    int d = idx & 31;
    int h = (idx >> 5) & 15;
    int t = (idx >> 9) & (TT-1);
    int b = idx >> 20;
    float c0 = cosT[t*HD + d],    s0 = sinT[t*HD + d];
    float c1 = cosT[t*HD + d+32], s1 = sinT[t*HD + d+32];
    long base = ((long)(b*TT + t))*3*CC + h*HD;
    // q
    float q0 = qkv[base + d], q1 = qkv[base + d + 32];
    qkv[base + d]      = q0*c0 - q1*s0;
    qkv[base + d + 32] = q1*c1 + q0*s1;
    // k
    base += CC;
    float k0 = qkv[base + d], k1 = qkv[base + d + 32];
    qkv[base + d]      = k0*c0 - k1*s0;
    qkv[base + d + 32] = k1*c1 + k0*s1;
}

// ------------------------------------------------------------------
// Causal flash attention, fp32.  Block = 64 query rows, one (b,h).
// dyn smem: Qs,Ks,Vs,Ss each 64x65 + m,l,alpha rows
// ------------------------------------------------------------------
#define ATT_SMEM ((4*64*65 + 3*64)*4)

__global__ void __launch_bounds__(256) attn_k(const float* __restrict__ qkv,
                                              float* __restrict__ y)
{
    extern __shared__ float sm[];
    float* Qs = sm;
    float* Ks = Qs + 64*65;
    float* Vs = Ks + 64*65;
    float* Ss = Vs + 64*65;
    float* mrow = Ss + 64*65;
    float* lrow = mrow + 64;
    float* arow = lrow + 64;

    int tid = threadIdx.x;
    int tr = tid >> 4, tc = tid & 15;      // 16x16 thread grid, 4x4 micro tile
    int qt = blockIdx.x, h = blockIdx.y, b = blockIdx.z;
    long base = ((long)b*TT)*3*CC + h*HD;

    // load Q tile (scaled by 1/sqrt(HD))
    #pragma unroll
    for (int i=0;i<4;i++){
        int id = tid + i*256;
        int r = id >> 4, dd = (id & 15)*4;
        float4 v = *(const float4*)(qkv + base + (long)(qt*64 + r)*3*CC + dd);
        Qs[r*65+dd]   = v.x*0.125f;
        Qs[r*65+dd+1] = v.y*0.125f;
        Qs[r*65+dd+2] = v.z*0.125f;
        Qs[r*65+dd+3] = v.w*0.125f;
    }
    if (tid < 64){ mrow[tid] = -1e30f; lrow[tid] = 0.f; }
    float acc[4][4] = {};
    __syncthreads();

    for (int jt=0; jt<=qt; jt++){
        // load K,V tiles
        #pragma unroll
        for (int i=0;i<4;i++){
            int id = tid + i*256;
            int r = id >> 4, dd = (id & 15)*4;
            long rb = base + (long)(jt*64 + r)*3*CC + dd;
            float4 kv = *(const float4*)(qkv + rb + CC);
            float4 vv = *(const float4*)(qkv + rb + 2*CC);
            Ks[r*65+dd]=kv.x; Ks[r*65+dd+1]=kv.y; Ks[r*65+dd+2]=kv.z; Ks[r*65+dd+3]=kv.w;
            Vs[r*65+dd]=vv.x; Vs[r*65+dd+1]=vv.y; Vs[r*65+dd+2]=vv.z; Vs[r*65+dd+3]=vv.w;
        }
        __syncthreads();
        // S = Q K^T
        float s[4][4] = {};
        #pragma unroll 8
        for (int d=0; d<HD; d++){
            float a0 = Qs[(tr*4+0)*65+d], a1 = Qs[(tr*4+1)*65+d];
            float a2 = Qs[(tr*4+2)*65+d], a3 = Qs[(tr*4+3)*65+d];
            float b0 = Ks[(tc*4+0)*65+d], b1 = Ks[(tc*4+1)*65+d];
            float b2 = Ks[(tc*4+2)*65+d], b3 = Ks[(tc*4+3)*65+d];
            s[0][0]+=a0*b0; s[0][1]+=a0*b1; s[0][2]+=a0*b2; s[0][3]+=a0*b3;
            s[1][0]+=a1*b0; s[1][1]+=a1*b1; s[1][2]+=a1*b2; s[1][3]+=a1*b3;
            s[2][0]+=a2*b0; s[2][1]+=a2*b1; s[2][2]+=a2*b2; s[2][3]+=a2*b3;
            s[3][0]+=a3*b0; s[3][1]+=a3*b1; s[3][2]+=a3*b2; s[3][3]+=a3*b3;
        }
        if (jt == qt){
            #pragma unroll
            for (int i=0;i<4;i++)
                #pragma unroll
                for (int j=0;j<4;j++)
                    if (tc*4+j > tr*4+i) s[i][j] = -1e30f;
        }
        #pragma unroll
        for (int i=0;i<4;i++)
            #pragma unroll
            for (int j=0;j<4;j++)
                Ss[(tr*4+i)*65 + tc*4+j] = s[i][j];
        __syncthreads();
        // row-wise online softmax update
        if (tid < 64){
            float mold = mrow[tid], mx = mold;
            #pragma unroll 8
            for (int j=0;j<64;j++) mx = fmaxf(mx, Ss[tid*65+j]);
            float al = __expf(mold - mx);
            float sum = 0.f;
            #pragma unroll 8
            for (int j=0;j<64;j++){
                float p = __expf(Ss[tid*65+j] - mx);
                Ss[tid*65+j] = p;
                sum += p;
            }
            mrow[tid] = mx;
            lrow[tid] = lrow[tid]*al + sum;
            arow[tid] = al;
        }
        __syncthreads();
        // O = O*alpha + P V
        #pragma unroll
        for (int i=0;i<4;i++){
            float al = arow[tr*4+i];
            acc[i][0]*=al; acc[i][1]*=al; acc[i][2]*=al; acc[i][3]*=al;
        }
        #pragma unroll 8
        for (int kk=0; kk<64; kk++){
            float p0 = Ss[(tr*4+0)*65+kk], p1 = Ss[(tr*4+1)*65+kk];
            float p2 = Ss[(tr*4+2)*65+kk], p3 = Ss[(tr*4+3)*65+kk];
            float v0 = Vs[kk*65 + tc*4+0], v1 = Vs[kk*65 + tc*4+1];
            float v2 = Vs[kk*65 + tc*4+2], v3 = Vs[kk*65 + tc*4+3];
            acc[0][0]+=p0*v0; acc[0][1]+=p0*v1; acc[0][2]+=p0*v2; acc[0][3]+=p0*v3;
            acc[1][0]+=p1*v0; acc[1][1]+=p1*v1; acc[1][2]+=p1*v2; acc[1][3]+=p1*v3;
            acc[2][0]+=p2*v0; acc[2][1]+=p2*v1; acc[2][2]+=p2*v2; acc[2][3]+=p2*v3;
            acc[3][0]+=p3*v0; acc[3][1]+=p3*v1; acc[3][2]+=p3*v2; acc[3][3]+=p3*v3;
        }
        __syncthreads();
    }
    // write y [B,T,C]
    #pragma unroll
    for (int i=0;i<4;i++){
        int t = qt*64 + tr*4 + i;
        float inv = 1.f / lrow[tr*4+i];
        long off = ((long)b*TT + t)*CC + h*HD + tc*4;
        y[off+0] = acc[i][0]*inv;
        y[off+1] = acc[i][1]*inv;
        y[off+2] = acc[i][2]*inv;
        y[off+3] = acc[i][3]*inv;
    }
}

// ------------------------------------------------------------------
// Generic tiled fp32 GEMM: C[m,n] = sum_k A[m,k] * B'(k,n)
//   TRANSB: B stored [N,K] (weights);  else [K,N]
// Epilogues (EPI):
//   0: acc
//   1: acc + bias[n]
//   2: silu(acc + bias[n])
//   3: sigmoid(acc + bias[n])
//   4: acc + bias[n] + ep0[idx]            (residual)
//   5: ep1[idx]*(ep0[idx] - acc*scale)     (v_dyn)
//   6: (ep0[idx] + acc)*scale              (mo)
// CAUSAL: zero where n>m (per batch), skip fully-masked blocks
// TRIA:   A is lower-triangular [M==K], clamp k-loop
// ------------------------------------------------------------------
template<int EPI, bool TRANSB, bool CAUSAL, bool TRIA>
__global__ void __launch_bounds__(256) gemm_k(
    const float* __restrict__ A, const float* __restrict__ Bm,
    const float* __restrict__ bias, const float* __restrict__ ep0,
    const float* __restrict__ ep1, float* __restrict__ C,
    int M, int N, int K, long sA, long sB, long sC, float scale)
{
    constexpr int BM=128, BN=64, BK=16;
    int m0 = blockIdx.y*BM, n0 = blockIdx.x*BN;
    long z = blockIdx.z;
    A  += z*sA;  Bm += z*sB;  C += z*sC;
    const float* e0 = ep0 ? ep0 + z*sC : (const float*)0;
    const float* e1 = ep1 ? ep1 + z*sC : (const float*)0;

    int tid = threadIdx.x;
    int tr = tid >> 4, tc = tid & 15;
    int row0 = tr*8, col0 = tc*4;

    if (CAUSAL && n0 > m0 + BM - 1){
        #pragma unroll
        for (int i=0;i<8;i++){
            long m = m0 + row0 + i;
            *(float4*)(C + m*N + n0 + col0) = make_float4(0.f,0.f,0.f,0.f);
        }
        return;
    }

    __shared__ float As[BK][BM];
    __shared__ float Bs[BK][BN];
    float acc[8][4] = {};

    int kmax = TRIA ? min(K, m0 + BM) : K;
    for (int k0=0; k0<kmax; k0+=BK){
        #pragma unroll
        for (int i=0;i<2;i++){
            int id = tid + i*256;
            int mm = id >> 2;
            int kk = (id & 3)*4;
            float4 v = *(const float4*)(A + (long)(m0+mm)*K + k0 + kk);
            As[kk  ][mm]=v.x; As[kk+1][mm]=v.y; As[kk+2][mm]=v.z; As[kk+3][mm]=v.w;
        }
        if (TRANSB){
            int nn = tid >> 2;
            int kk = (tid & 3)*4;
            float4 v = *(const float4*)(Bm + (long)(n0+nn)*K + k0 + kk);
            Bs[kk  ][nn]=v.x; Bs[kk+1][nn]=v.y; Bs[kk+2][nn]=v.z; Bs[kk+3][nn]=v.w;
        } else {
            int kk = tid >> 4;
            int nn = (tid & 15)*4;
            *(float4*)&Bs[kk][nn] = *(const float4*)(Bm + (long)(k0+kk)*N + n0 + nn);
        }
        __syncthreads();
        #pragma unroll
        for (int k=0;k<BK;k++){
            float4 a0 = *(float4*)&As[k][row0];
            float4 a1 = *(float4*)&As[k][row0+4];
            float4 bv = *(float4*)&Bs[k][col0];
            float av[8] = {a0.x,a0.y,a0.z,a0.w,a1.x,a1.y,a1.z,a1.w};
            float bb[4] = {bv.x,bv.y,bv.z,bv.w};
            #pragma unroll
            for (int i=0;i<8;i++)
                #pragma unroll
                for (int j=0;j<4;j++)
                    acc[i][j] = fmaf(av[i], bb[j], acc[i][j]);
        }
        __syncthreads();
    }

    #pragma unroll
    for (int i=0;i<8;i++){
        int m = m0 + row0 + i;
        long rowoff = (long)m*N;
        #pragma unroll
        for (int j=0;j<4;j++){
            int n = n0 + col0 + j;
            long idx = rowoff + n;
            float v = acc[i][j];
            if (EPI==1)      v += bias[n];
            else if (EPI==2){ v += bias[n]; v = v * sigm(v); }
            else if (EPI==3){ v = sigm(v + bias[n]); }
            else if (EPI==4){ v += bias[n] + e0[idx]; }
            else if (EPI==5){ v = e1[idx]*(e0[idx] - v*scale); }
            else if (EPI==6){ v = (e0[idx] + v)*scale; }
            if (CAUSAL && n > m) v = 0.f;
            C[idx] = v;
        }
    }
}

// ------------------------------------------------------------------
// Launcher (one-time host-side memoized setup; capture-safe)
// ------------------------------------------------------------------
static float *p_h, *p_ffnh, *p_xffn, *p_qkv, *p_y, *p_s, *p_mc, *p_cq,
             *p_ck, *p_cv, *p_cg, *p_vdyn, *p_mo, *p_woh;
static bool  s_init = false;

extern "C" void kernel_launch(void* const* d_in, const int* in_sizes, int n_in,
                              void* d_out, int out_size)
{
    (void)in_sizes; (void)n_in; (void)out_size;
    const float* x      = (const float*)d_in[0];
    const float* cosT   = (const float*)d_in[1];
    const float* sinT   = (const float*)d_in[2];
    const float* qkv_w  = (const float*)d_in[3];
    const float* proj_w = (const float*)d_in[4];
    const float* proj_b = (const float*)d_in[5];
    const float* norm_g = (const float*)d_in[6];
    const float* norm_b = (const float*)d_in[7];
    const float* anorm_g= (const float*)d_in[8];
    const float* anorm_b= (const float*)d_in[9];
    const float* ffn1_w = (const float*)d_in[10];
    const float* ffn1_b = (const float*)d_in[11];
    const float* ffn2_w = (const float*)d_in[12];
    const float* ffn2_b = (const float*)d_in[13];
    const float* mem    = (const float*)d_in[14];
    // d_in[15..18]: memg_w, memg_b, mnorm_g, mnorm_b
    const float* mnorm_g= (const float*)d_in[17];
    const float* mnorm_b= (const float*)d_in[18];
    const float* wq_w   = (const float*)d_in[19];
    const float* wq_b   = (const float*)d_in[20];
    const float* wk_w   = (const float*)d_in[21];
    const float* wk_b   = (const float*)d_in[22];
    const float* wv_w   = (const float*)d_in[23];
    const float* wv_b   = (const float*)d_in[24];
    const float* wg_w   = (const float*)d_in[25];
    const float* wg_b   = (const float*)d_in[26];
    const float* wo_w   = (const float*)d_in[27];
    const float* wo_b   = (const float*)d_in[28];
    const float* op_w   = (const float*)d_in[29];
    const float* op_b   = (const float*)d_in[30];

    if (!s_init){
        cudaGetSymbolAddress((void**)&p_h,    g_h);
        cudaGetSymbolAddress((void**)&p_ffnh, g_ffnh);
        cudaGetSymbolAddress((void**)&p_xffn, g_xffn);
        cudaGetSymbolAddress((void**)&p_qkv,  g_qkv);
        cudaGetSymbolAddress((void**)&p_y,    g_y);
        cudaGetSymbolAddress((void**)&p_s,    g_s);
        cudaGetSymbolAddress((void**)&p_mc,   g_mc);
        cudaGetSymbolAddress((void**)&p_cq,   g_cq);
        cudaGetSymbolAddress((void**)&p_ck,   g_ck);
        cudaGetSymbolAddress((void**)&p_cv,   g_cv);
        cudaGetSymbolAddress((void**)&p_cg,   g_cg);
        cudaGetSymbolAddress((void**)&p_vdyn, g_vdyn);
        cudaGetSymbolAddress((void**)&p_mo,   g_mo);
        cudaGetSymbolAddress((void**)&p_woh,  g_woh);
        cudaFuncSetAttribute(attn_k, cudaFuncAttributeMaxDynamicSharedMemorySize, ATT_SMEM);
        s_init = true;
    }
    float *h=p_h, *ffnh=p_ffnh, *xffn=p_xffn, *qkv=p_qkv, *y=p_y, *s=p_s,
          *mc=p_mc, *cq=p_cq, *ck=p_ck, *cv=p_cv, *cg=p_cg, *vdyn=p_vdyn,
          *mo=p_mo, *woh=p_woh;

    float* out    = (float*)d_out;
    float* out_sc = out + (long)MM*CC;

    // 1) h = LN(x)
    ln_k<<<MM,256>>>(x, norm_g, norm_b, h);
    // 2) ffnh = silu(h @ ffn1_w^T + b1)
    gemm_k<2,true,false,false><<<dim3(FHID/64, MM/128, 1),256>>>(
        h, ffn1_w, ffn1_b, 0, 0, ffnh, MM, FHID, CC, 0,0,0, 0.f);
    // 3) x_ffn = x + ffnh @ ffn2_w^T + b2
    gemm_k<4,true,false,false><<<dim3(CC/64, MM/128, 1),256>>>(
        ffnh, ffn2_w, ffn2_b, x, 0, xffn, MM, CC, FHID, 0,0,0, 0.f);
    // 4) h = LN(x_ffn)
    ln_k<<<MM,256>>>(xffn, anorm_g, anorm_b, h);
    // 5) qkv = h @ qkv_w^T
    gemm_k<0,true,false,false><<<dim3(3*CC/64, MM/128, 1),256>>>(
        h, qkv_w, 0, 0, 0, qkv, MM, 3*CC, CC, 0,0,0, 0.f);
    // 6) RoPE on q,k
    rope_k<<<(BB*TT*HH*32 + 255)/256, 256>>>(qkv, cosT, sinT);
    // 7) causal attention -> y
    attn_k<<<dim3(TT/64, HH, BB), 256, ATT_SMEM>>>(qkv, y);
    // 8) s = x_ffn + y @ proj_w^T + proj_b
    gemm_k<4,true,false,false><<<dim3(CC/64, MM/128, 1),256>>>(
        y, proj_w, proj_b, xffn, 0, s, MM, CC, CC, 0,0,0, 0.f);
    // 9) mc = LN(s)
    ln_k<<<MM,256>>>(s, mnorm_g, mnorm_b, mc);
    // 10-13) cq/ck/cv/cg
    gemm_k<2,true,false,false><<<dim3(CC/64, MM/128, 1),256>>>(
        mc, wq_w, wq_b, 0, 0, cq, MM, CC, CC, 0,0,0, 0.f);
    gemm_k<1,true,false,false><<<dim3(CC/64, MM/128, 1),256>>>(
        mc, wk_w, wk_b, 0, 0, ck, MM, CC, CC, 0,0,0, 0.f);
    gemm_k<1,true,false,false><<<dim3(CC/64, MM/128, 1),256>>>(
        mc, wv_w, wv_b, 0, 0, cv, MM, CC, CC, 0,0,0, 0.f);
    gemm_k<3,true,false,false><<<dim3(CC/64, MM/128, 1),256>>>(
        mc, wg_w, wg_b, 0, 0, cg, MM, CC, CC, 0,0,0, 0.f);
    // 14) ck row-normalize
    knorm_k<<<MM,256>>>(ck);
    // 15) v_dyn = cg*(cv - (ck@mem)*scale)
    gemm_k<5,false,false,false><<<dim3(CC/64, MM/128, 1),256>>>(
        ck, mem, 0, cv, cg, vdyn, MM, CC, CC, 0,0,0, MSCALE);
    // 16) mo = cq @ mem   (mo_prev, unscaled)
    gemm_k<0,false,false,false><<<dim3(CC/64, MM/128, 1),256>>>(
        cq, mem, 0, 0, 0, mo, MM, CC, CC, 0,0,0, 0.f);
    // 17) sc_c = tril(cq @ ck^T)  (batched per b) -> second output
    gemm_k<0,true,true,false><<<dim3(TT/64, TT/128, BB),256>>>(
        cq, ck, 0, 0, 0, out_sc, TT, TT, CC,
        (long)TT*CC, (long)TT*CC, (long)TT*TT, 0.f);
    // 18) mo = (mo_prev + sc_c @ v_dyn) * scale   (batched, triangular A)
    gemm_k<6,false,false,true><<<dim3(CC/64, TT/128, BB),256>>>(
        out_sc, vdyn, 0, mo, 0, mo, TT, CC, TT,
        (long)TT*TT, (long)TT*CC, (long)TT*CC, MSCALE);
    // 19) woh = silu(mo @ wo_w^T + wo_b)
    gemm_k<2,true,false,false><<<dim3(4*CC/64, MM/128, 1),256>>>(
        mo, wo_w, wo_b, 0, 0, woh, MM, 4*CC, CC, 0,0,0, 0.f);
    // 20) out = s + woh @ op_w^T + op_b
    gemm_k<4,true,false,false><<<dim3(CC/64, MM/128, 1),256>>>(
        woh, op_w, op_b, s, 0, out, MM, CC, 4*CC, 0,0,0, 0.f);
}

// round 4
// speedup vs baseline: 2.3873x; 2.3873x over previous
#include <cuda_runtime.h>
#include <cuda_bf16.h>
#include <math.h>

// Problem constants
#define BB 2
#define TT 2048
#define CC 1024
#define HH 16
#define HD 64
#define FHID 1536
#define MM (BB*TT)          // 4096
#define MSCALE 0.03125f     // 1/sqrt(1024)

// ------------------------------------------------------------------
// Scratch (static device globals — no allocation allowed)
// ------------------------------------------------------------------
__device__ float g_h   [MM*CC];
__device__ float g_ffnh[MM*FHID];
__device__ float g_xffn[MM*CC];
__device__ float g_qkv [MM*3*CC];
__device__ float g_y   [MM*CC];
__device__ float g_s   [MM*CC];
__device__ float g_mc  [MM*CC];
__device__ float g_cq  [MM*CC];
__device__ float g_ck  [MM*CC];
__device__ float g_cv  [MM*CC];
__device__ float g_cg  [MM*CC];
__device__ float g_vdyn[MM*CC];
__device__ float g_mo  [MM*CC];
__device__ float g_woh [MM*4*CC];

__device__ __forceinline__ float sigm(float x){ return 1.f/(1.f+__expf(-x)); }

// ------------------------------------------------------------------
// LayerNorm
// ------------------------------------------------------------------
__global__ void __launch_bounds__(256) ln_k(const float* __restrict__ x,
                                            const float* __restrict__ g,
                                            const float* __restrict__ b,
                                            float* __restrict__ out)
{
    __shared__ float sa[8], sb[8];
    int row = blockIdx.x, tid = threadIdx.x;
    const float* xr = x + (long)row*CC;
    float4 v = *(const float4*)(xr + tid*4);
    float s = v.x+v.y+v.z+v.w;
    float q = v.x*v.x + v.y*v.y + v.z*v.z + v.w*v.w;
    int lane = tid & 31, wid = tid >> 5;
    #pragma unroll
    for (int o=16;o;o>>=1){ s += __shfl_down_sync(~0u,s,o); q += __shfl_down_sync(~0u,q,o); }
    if (lane==0){ sa[wid]=s; sb[wid]=q; }
    __syncthreads();
    if (tid==0){ float ss=0,qq=0; for(int i=0;i<8;i++){ss+=sa[i];qq+=sb[i];} sa[0]=ss; sb[0]=qq; }
    __syncthreads();
    float mean = sa[0]*(1.f/CC);
    float var  = sb[0]*(1.f/CC) - mean*mean;
    float rstd = rsqrtf(var + 1e-5f);
    float4 gv = *(const float4*)(g + tid*4);
    float4 bv = *(const float4*)(b + tid*4);
    float4 o;
    o.x = (v.x-mean)*rstd*gv.x + bv.x;
    o.y = (v.y-mean)*rstd*gv.y + bv.y;
    o.z = (v.z-mean)*rstd*gv.z + bv.z;
    o.w = (v.w-mean)*rstd*gv.w + bv.w;
    *(float4*)(out + (long)row*CC + tid*4) = o;
}

// ------------------------------------------------------------------
// Row L2-normalize in place (ck)
// ------------------------------------------------------------------
__global__ void __launch_bounds__(256) knorm_k(float* __restrict__ ck)
{
    __shared__ float sb[8];
    int row = blockIdx.x, tid = threadIdx.x;
    float* xr = ck + (long)row*CC;
    float4 v = *(const float4*)(xr + tid*4);
    float q = v.x*v.x + v.y*v.y + v.z*v.z + v.w*v.w;
    int lane = tid & 31, wid = tid >> 5;
    #pragma unroll
    for (int o=16;o;o>>=1) q += __shfl_down_sync(~0u,q,o);
    if (lane==0) sb[wid]=q;
    __syncthreads();
    if (tid==0){ float qq=0; for(int i=0;i<8;i++) qq+=sb[i]; sb[0]=qq; }
    __syncthreads();
    float inv = 1.f / fmaxf(sqrtf(sb[0]), 1e-5f);
    v.x*=inv; v.y*=inv; v.z*=inv; v.w*=inv;
    *(float4*)(xr + tid*4) = v;
}

// ------------------------------------------------------------------
// RoPE on q and k inside qkv buffer (in-place)
// ------------------------------------------------------------------
__global__ void __launch_bounds__(256) rope_k(float* __restrict__ qkv,
                                              const float* __restrict__ cosT,
                                              const float* __restrict__ sinT)
{
    int idx = blockIdx.x*blockDim.x + threadIdx.x;
    if (idx >= BB*TT*HH*32) return;
    int d = idx & 31;
    int h = (idx >> 5) & 15;
    int t = (idx >> 9) & (TT-1);
    int b = idx >> 20;
    float c0 = cosT[t*HD + d],    s0 = sinT[t*HD + d];
    float c1 = cosT[t*HD + d+32], s1 = sinT[t*HD + d+32];
    long base = ((long)(b*TT + t))*3*CC + h*HD;
    float q0 = qkv[base + d], q1 = qkv[base + d + 32];
    qkv[base + d]      = q0*c0 - q1*s0;
    qkv[base + d + 32] = q1*c1 + q0*s1;
    base += CC;
    float k0 = qkv[base + d], k1 = qkv[base + d + 32];
    qkv[base + d]      = k0*c0 - k1*s0;
    qkv[base + d + 32] = k1*c1 + k0*s1;
}

// ------------------------------------------------------------------
// Causal flash attention, fp32 (unchanged this round)
// ------------------------------------------------------------------
#define ATT_SMEM ((4*64*65 + 3*64)*4)

__global__ void __launch_bounds__(256) attn_k(const float* __restrict__ qkv,
                                              float* __restrict__ y)
{
    extern __shared__ float sm[];
    float* Qs = sm;
    float* Ks = Qs + 64*65;
    float* Vs = Ks + 64*65;
    float* Ss = Vs + 64*65;
    float* mrow = Ss + 64*65;
    float* lrow = mrow + 64;
    float* arow = lrow + 64;

    int tid = threadIdx.x;
    int tr = tid >> 4, tc = tid & 15;
    int qt = blockIdx.x, h = blockIdx.y, b = blockIdx.z;
    long base = ((long)b*TT)*3*CC + h*HD;

    #pragma unroll
    for (int i=0;i<4;i++){
        int id = tid + i*256;
        int r = id >> 4, dd = (id & 15)*4;
        float4 v = *(const float4*)(qkv + base + (long)(qt*64 + r)*3*CC + dd);
        Qs[r*65+dd]   = v.x*0.125f;
        Qs[r*65+dd+1] = v.y*0.125f;
        Qs[r*65+dd+2] = v.z*0.125f;
        Qs[r*65+dd+3] = v.w*0.125f;
    }
    if (tid < 64){ mrow[tid] = -1e30f; lrow[tid] = 0.f; }
    float acc[4][4] = {};
    __syncthreads();

    for (int jt=0; jt<=qt; jt++){
        #pragma unroll
        for (int i=0;i<4;i++){
            int id = tid + i*256;
            int r = id >> 4, dd = (id & 15)*4;
            long rb = base + (long)(jt*64 + r)*3*CC + dd;
            float4 kv = *(const float4*)(qkv + rb + CC);
            float4 vv = *(const float4*)(qkv + rb + 2*CC);
            Ks[r*65+dd]=kv.x; Ks[r*65+dd+1]=kv.y; Ks[r*65+dd+2]=kv.z; Ks[r*65+dd+3]=kv.w;
            Vs[r*65+dd]=vv.x; Vs[r*65+dd+1]=vv.y; Vs[r*65+dd+2]=vv.z; Vs[r*65+dd+3]=vv.w;
        }
        __syncthreads();
        float s[4][4] = {};
        #pragma unroll 8
        for (int d=0; d<HD; d++){
            float a0 = Qs[(tr*4+0)*65+d], a1 = Qs[(tr*4+1)*65+d];
            float a2 = Qs[(tr*4+2)*65+d], a3 = Qs[(tr*4+3)*65+d];
            float b0 = Ks[(tc*4+0)*65+d], b1 = Ks[(tc*4+1)*65+d];
            float b2 = Ks[(tc*4+2)*65+d], b3 = Ks[(tc*4+3)*65+d];
            s[0][0]+=a0*b0; s[0][1]+=a0*b1; s[0][2]+=a0*b2; s[0][3]+=a0*b3;
            s[1][0]+=a1*b0; s[1][1]+=a1*b1; s[1][2]+=a1*b2; s[1][3]+=a1*b3;
            s[2][0]+=a2*b0; s[2][1]+=a2*b1; s[2][2]+=a2*b2; s[2][3]+=a2*b3;
            s[3][0]+=a3*b0; s[3][1]+=a3*b1; s[3][2]+=a3*b2; s[3][3]+=a3*b3;
        }
        if (jt == qt){
            #pragma unroll
            for (int i=0;i<4;i++)
                #pragma unroll
                for (int j=0;j<4;j++)
                    if (tc*4+j > tr*4+i) s[i][j] = -1e30f;
        }
        #pragma unroll
        for (int i=0;i<4;i++)
            #pragma unroll
            for (int j=0;j<4;j++)
                Ss[(tr*4+i)*65 + tc*4+j] = s[i][j];
        __syncthreads();
        if (tid < 64){
            float mold = mrow[tid], mx = mold;
            #pragma unroll 8
            for (int j=0;j<64;j++) mx = fmaxf(mx, Ss[tid*65+j]);
            float al = __expf(mold - mx);
            float sum = 0.f;
            #pragma unroll 8
            for (int j=0;j<64;j++){
                float p = __expf(Ss[tid*65+j] - mx);
                Ss[tid*65+j] = p;
                sum += p;
            }
            mrow[tid] = mx;
            lrow[tid] = lrow[tid]*al + sum;
            arow[tid] = al;
        }
        __syncthreads();
        #pragma unroll
        for (int i=0;i<4;i++){
            float al = arow[tr*4+i];
            acc[i][0]*=al; acc[i][1]*=al; acc[i][2]*=al; acc[i][3]*=al;
        }
        #pragma unroll 8
        for (int kk=0; kk<64; kk++){
            float p0 = Ss[(tr*4+0)*65+kk], p1 = Ss[(tr*4+1)*65+kk];
            float p2 = Ss[(tr*4+2)*65+kk], p3 = Ss[(tr*4+3)*65+kk];
            float v0 = Vs[kk*65 + tc*4+0], v1 = Vs[kk*65 + tc*4+1];
            float v2 = Vs[kk*65 + tc*4+2], v3 = Vs[kk*65 + tc*4+3];
            acc[0][0]+=p0*v0; acc[0][1]+=p0*v1; acc[0][2]+=p0*v2; acc[0][3]+=p0*v3;
            acc[1][0]+=p1*v0; acc[1][1]+=p1*v1; acc[1][2]+=p1*v2; acc[1][3]+=p1*v3;
            acc[2][0]+=p2*v0; acc[2][1]+=p2*v1; acc[2][2]+=p2*v2; acc[2][3]+=p2*v3;
            acc[3][0]+=p3*v0; acc[3][1]+=p3*v1; acc[3][2]+=p3*v2; acc[3][3]+=p3*v3;
        }
        __syncthreads();
    }
    #pragma unroll
    for (int i=0;i<4;i++){
        int t = qt*64 + tr*4 + i;
        float inv = 1.f / lrow[tr*4+i];
        long off = ((long)b*TT + t)*CC + h*HD + tc*4;
        y[off+0] = acc[i][0]*inv;
        y[off+1] = acc[i][1]*inv;
        y[off+2] = acc[i][2]*inv;
        y[off+3] = acc[i][3]*inv;
    }
}

// ==================================================================
// TF32 tensor-core GEMM.
// BM=BN=128, BK=32, 128 threads (4 warps 2x2), warp tile 64x64.
// SMEM holds fragment-packed tf32 tiles: each lane's 4 mma regs are
// one 16B unit -> LDS.128 fragment loads. XOR swizzle + 132-pad rows.
// ==================================================================
#define GEMM_SMEM (4*4224*4)   // 2 A bufs + 2 B bufs, 4224 u32 each = 67584 B

__device__ __forceinline__ void mma_tf32(float* c, const uint4& a, unsigned b0, unsigned b1)
{
    asm volatile(
        "mma.sync.aligned.m16n8k8.row.col.f32.tf32.tf32.f32 "
        "{%0,%1,%2,%3},{%4,%5,%6,%7},{%8,%9},{%0,%1,%2,%3};\n"
        : "+f"(c[0]), "+f"(c[1]), "+f"(c[2]), "+f"(c[3])
        : "r"(a.x), "r"(a.y), "r"(a.z), "r"(a.w), "r"(b0), "r"(b1));
}

__device__ __forceinline__ unsigned f2tf32(unsigned fbits)
{
    unsigned t;
    asm("cvt.rna.tf32.f32 %0, %1;" : "=r"(t) : "f"(__uint_as_float(fbits)));
    return t;
}

template<int EPI, bool TRANSB, bool CAUSAL, bool TRIA>
__global__ void __launch_bounds__(128) gemm_tc(
    const float* __restrict__ A, const float* __restrict__ Bm,
    const float* __restrict__ bias, const float* __restrict__ ep0,
    const float* __restrict__ ep1, float* __restrict__ C,
    int M, int N, int K, long sA, long sB, long sC, float scale)
{
    constexpr int BM=128, BK=32;
    int m0 = blockIdx.y*BM, n0 = blockIdx.x*128;
    long z = blockIdx.z;
    A  += z*sA;  Bm += z*sB;  C += z*sC;
    const float* e0 = ep0 ? ep0 + z*sC : (const float*)0;
    const float* e1 = ep1 ? ep1 + z*sC : (const float*)0;

    int tid  = threadIdx.x;
    int lane = tid & 31;
    int wid  = tid >> 5;
    int wm   = wid >> 1, wn = wid & 1;
    int g    = lane >> 2, tig = lane & 3;

    // ---------- fully-masked causal block: exact zero fill ----------
    if (CAUSAL && n0 > m0 + BM - 1){
        #pragma unroll
        for (int mt=0;mt<4;mt++)
        #pragma unroll
        for (int p=0;p<4;p++)
        #pragma unroll
        for (int sub=0;sub<2;sub++){
            int col = n0 + wn*64 + p*16 + sub*8 + tig*2;
            #pragma unroll
            for (int half=0;half<2;half++){
                int row = m0 + wm*64 + mt*16 + g + half*8;
                *(float2*)(C + (long)row*N + col) = make_float2(0.f,0.f);
            }
        }
        return;
    }

    extern __shared__ unsigned smem_u[];
    unsigned* Abuf[2] = { smem_u,          smem_u + 4224 };
    unsigned* Bbuf[2] = { smem_u + 8448,   smem_u + 12672 };

    float acc[4][4][2][4];
    #pragma unroll
    for (int a=0;a<4;a++) for (int b=0;b<4;b++) for (int c=0;c<2;c++) for (int d=0;d<4;d++)
        acc[a][b][c][d] = 0.f;

    int kmax = TRIA ? min(K, m0 + BM) : K;
    int nchunks = kmax / BK;

    uint4 ra[8], rb[8];

    // ---- global loaders (into regs) ----
    auto ldgA = [&](int c){
        long kb = (long)c*BK;
        #pragma unroll
        for (int i=0;i<8;i++){
            int m = (tid>>3) + i*16;
            ra[i] = *(const uint4*)(A + (long)(m0+m)*K + kb + (tid&7)*4);
        }
    };
    auto ldgB = [&](int c){
        long kb = (long)c*BK;
        if (TRANSB){
            #pragma unroll
            for (int i=0;i<8;i++){
                int n = (tid>>3) + i*16;
                rb[i] = *(const uint4*)(Bm + (long)(n0+n)*K + kb + (tid&7)*4);
            }
        } else {
            #pragma unroll
            for (int i=0;i<8;i++){
                int k = (tid>>5) + i*4;
                rb[i] = *(const uint4*)(Bm + (kb + k)*(long)N + n0 + (tid&31)*4);
            }
        }
    };

    // ---- STS into fragment-packed layout ----
    auto stsA = [&](int buf){
        unsigned* dst = Abuf[buf];
        #pragma unroll
        for (int i=0;i<8;i++){
            int m  = (tid>>3) + i*16;
            int kk = (tid&7)*4;
            unsigned vals[4] = { ra[i].x, ra[i].y, ra[i].z, ra[i].w };
            #pragma unroll
            for (int j=0;j<4;j++){
                int kl = kk + j;
                int ul = (m&7)*4 + j;
                int up = ul ^ (ul>>3);
                int r  = ((m>>3)&1) + 2*((kl>>2)&1);
                dst[((kl>>3)*8 + (m>>4))*132 + up*4 + r] = f2tf32(vals[j]);
            }
        }
    };
    auto stsB = [&](int buf){
        unsigned* dst = Bbuf[buf];
        if (TRANSB){
            #pragma unroll
            for (int i=0;i<8;i++){
                int n  = (tid>>3) + i*16;
                int kk = (tid&7)*4;
                unsigned vals[4] = { rb[i].x, rb[i].y, rb[i].z, rb[i].w };
                #pragma unroll
                for (int j=0;j<4;j++){
                    int kl = kk + j;
                    int ul = (n&7)*4 + (kl&3);
                    int up = ul ^ (ul>>3);
                    int r  = ((kl>>2)&1) + 2*((n>>3)&1);
                    dst[((kl>>3)*8 + (n>>4))*132 + up*4 + r] = f2tf32(vals[j]);
                }
            }
        } else {
            #pragma unroll
            for (int i=0;i<8;i++){
                int k  = (tid>>5) + i*4;
                int nn = (tid&31)*4;
                unsigned vals[4] = { rb[i].x, rb[i].y, rb[i].z, rb[i].w };
                #pragma unroll
                for (int j=0;j<4;j++){
                    int n  = nn + j;
                    int ul = (n&7)*4 + (k&3);
                    int up = ul ^ (ul>>3);
                    int r  = ((k>>2)&1) + 2*((n>>3)&1);
                    dst[((k>>3)*8 + (n>>4))*132 + up*4 + r] = f2tf32(vals[j]);
                }
            }
        }
    };

    int up4 = (lane ^ (lane>>3))*4;

    auto compute = [&](int buf){
        const unsigned* As = Abuf[buf];
        const unsigned* Bs = Bbuf[buf];
        #pragma unroll
        for (int ks=0;ks<4;ks++){
            uint4 af[4], bf[4];
            #pragma unroll
            for (int mt=0;mt<4;mt++)
                af[mt] = *(const uint4*)&As[(ks*8 + wm*4 + mt)*132 + up4];
            #pragma unroll
            for (int p=0;p<4;p++)
                bf[p] = *(const uint4*)&Bs[(ks*8 + wn*4 + p)*132 + up4];
            #pragma unroll
            for (int mt=0;mt<4;mt++)
                #pragma unroll
                for (int p=0;p<4;p++){
                    mma_tf32(acc[mt][p][0], af[mt], bf[p].x, bf[p].y);
                    mma_tf32(acc[mt][p][1], af[mt], bf[p].z, bf[p].w);
                }
        }
    };

    // ---- pipeline ----
    ldgA(0); ldgB(0);
    stsA(0); stsB(0);
    __syncthreads();
    for (int c=0;c<nchunks;c++){
        if (c+1 < nchunks){ ldgA(c+1); ldgB(c+1); }
        compute(c&1);
        if (c+1 < nchunks){
            __syncthreads();
            stsA((c+1)&1); stsB((c+1)&1);
            __syncthreads();
        }
    }

    // ---- epilogue ----
    #pragma unroll
    for (int mt=0;mt<4;mt++)
    #pragma unroll
    for (int p=0;p<4;p++)
    #pragma unroll
    for (int sub=0;sub<2;sub++){
        int col = n0 + wn*64 + p*16 + sub*8 + tig*2;
        float2 bv = make_float2(0.f,0.f);
        if (EPI>=1 && EPI<=4) bv = *(const float2*)(bias + col);
        #pragma unroll
        for (int half=0;half<2;half++){
            int row = m0 + wm*64 + mt*16 + g + half*8;
            long idx = (long)row*N + col;
            float v0 = acc[mt][p][sub][half*2+0];
            float v1 = acc[mt][p][sub][half*2+1];
            if (EPI==1){ v0 += bv.x; v1 += bv.y; }
            else if (EPI==2){ v0 += bv.x; v1 += bv.y; v0 = v0*sigm(v0); v1 = v1*sigm(v1); }
            else if (EPI==3){ v0 = sigm(v0+bv.x); v1 = sigm(v1+bv.y); }
            else if (EPI==4){ float2 e = *(const float2*)(e0+idx); v0 += bv.x + e.x; v1 += bv.y + e.y; }
            else if (EPI==5){ float2 a = *(const float2*)(e0+idx); float2 gg = *(const float2*)(e1+idx);
                              v0 = gg.x*(a.x - v0*scale); v1 = gg.y*(a.y - v1*scale); }
            else if (EPI==6){ float2 a = *(const float2*)(e0+idx);
                              v0 = (a.x + v0)*scale; v1 = (a.y + v1)*scale; }
            if (CAUSAL){
                if (col   > row) v0 = 0.f;
                if (col+1 > row) v1 = 0.f;
            }
            *(float2*)(C + idx) = make_float2(v0, v1);
        }
    }
}

// ------------------------------------------------------------------
// Launcher
// ------------------------------------------------------------------
static float *p_h, *p_ffnh, *p_xffn, *p_qkv, *p_y, *p_s, *p_mc, *p_cq,
             *p_ck, *p_cv, *p_cg, *p_vdyn, *p_mo, *p_woh;
static bool  s_init = false;

extern "C" void kernel_launch(void* const* d_in, const int* in_sizes, int n_in,
                              void* d_out, int out_size)
{
    (void)in_sizes; (void)n_in; (void)out_size;
    const float* x      = (const float*)d_in[0];
    const float* cosT   = (const float*)d_in[1];
    const float* sinT   = (const float*)d_in[2];
    const float* qkv_w  = (const float*)d_in[3];
    const float* proj_w = (const float*)d_in[4];
    const float* proj_b = (const float*)d_in[5];
    const float* norm_g = (const float*)d_in[6];
    const float* norm_b = (const float*)d_in[7];
    const float* anorm_g= (const float*)d_in[8];
    const float* anorm_b= (const float*)d_in[9];
    const float* ffn1_w = (const float*)d_in[10];
    const float* ffn1_b = (const float*)d_in[11];
    const float* ffn2_w = (const float*)d_in[12];
    const float* ffn2_b = (const float*)d_in[13];
    const float* mem    = (const float*)d_in[14];
    const float* mnorm_g= (const float*)d_in[17];
    const float* mnorm_b= (const float*)d_in[18];
    const float* wq_w   = (const float*)d_in[19];
    const float* wq_b   = (const float*)d_in[20];
    const float* wk_w   = (const float*)d_in[21];
    const float* wk_b   = (const float*)d_in[22];
    const float* wv_w   = (const float*)d_in[23];
    const float* wv_b   = (const float*)d_in[24];
    const float* wg_w   = (const float*)d_in[25];
    const float* wg_b   = (const float*)d_in[26];
    const float* wo_w   = (const float*)d_in[27];
    const float* wo_b   = (const float*)d_in[28];
    const float* op_w   = (const float*)d_in[29];
    const float* op_b   = (const float*)d_in[30];

    if (!s_init){
        cudaGetSymbolAddress((void**)&p_h,    g_h);
        cudaGetSymbolAddress((void**)&p_ffnh, g_ffnh);
        cudaGetSymbolAddress((void**)&p_xffn, g_xffn);
        cudaGetSymbolAddress((void**)&p_qkv,  g_qkv);
        cudaGetSymbolAddress((void**)&p_y,    g_y);
        cudaGetSymbolAddress((void**)&p_s,    g_s);
        cudaGetSymbolAddress((void**)&p_mc,   g_mc);
        cudaGetSymbolAddress((void**)&p_cq,   g_cq);
        cudaGetSymbolAddress((void**)&p_ck,   g_ck);
        cudaGetSymbolAddress((void**)&p_cv,   g_cv);
        cudaGetSymbolAddress((void**)&p_cg,   g_cg);
        cudaGetSymbolAddress((void**)&p_vdyn, g_vdyn);
        cudaGetSymbolAddress((void**)&p_mo,   g_mo);
        cudaGetSymbolAddress((void**)&p_woh,  g_woh);
        cudaFuncSetAttribute(attn_k, cudaFuncAttributeMaxDynamicSharedMemorySize, ATT_SMEM);
        {
            auto* f0 = gemm_tc<0,true ,false,false>;
            auto* f1 = gemm_tc<1,true ,false,false>;
            auto* f2 = gemm_tc<2,true ,false,false>;
            auto* f3 = gemm_tc<3,true ,false,false>;
            auto* f4 = gemm_tc<4,true ,false,false>;
            auto* f5 = gemm_tc<5,false,false,false>;
            auto* f6 = gemm_tc<0,false,false,false>;
            auto* f7 = gemm_tc<0,true ,true ,false>;
            auto* f8 = gemm_tc<6,false,false,true >;
            cudaFuncSetAttribute(f0, cudaFuncAttributeMaxDynamicSharedMemorySize, GEMM_SMEM);
            cudaFuncSetAttribute(f1, cudaFuncAttributeMaxDynamicSharedMemorySize, GEMM_SMEM);
            cudaFuncSetAttribute(f2, cudaFuncAttributeMaxDynamicSharedMemorySize, GEMM_SMEM);
            cudaFuncSetAttribute(f3, cudaFuncAttributeMaxDynamicSharedMemorySize, GEMM_SMEM);
            cudaFuncSetAttribute(f4, cudaFuncAttributeMaxDynamicSharedMemorySize, GEMM_SMEM);
            cudaFuncSetAttribute(f5, cudaFuncAttributeMaxDynamicSharedMemorySize, GEMM_SMEM);
            cudaFuncSetAttribute(f6, cudaFuncAttributeMaxDynamicSharedMemorySize, GEMM_SMEM);
            cudaFuncSetAttribute(f7, cudaFuncAttributeMaxDynamicSharedMemorySize, GEMM_SMEM);
            cudaFuncSetAttribute(f8, cudaFuncAttributeMaxDynamicSharedMemorySize, GEMM_SMEM);
        }
        s_init = true;
    }
    float *h=p_h, *ffnh=p_ffnh, *xffn=p_xffn, *qkv=p_qkv, *y=p_y, *s=p_s,
          *mc=p_mc, *cq=p_cq, *ck=p_ck, *cv=p_cv, *cg=p_cg, *vdyn=p_vdyn,
          *mo=p_mo, *woh=p_woh;

    float* out    = (float*)d_out;
    float* out_sc = out + (long)MM*CC;

    // 1) h = LN(x)
    ln_k<<<MM,256>>>(x, norm_g, norm_b, h);
    // 2) ffnh = silu(h @ ffn1_w^T + b1)
    gemm_tc<2,true,false,false><<<dim3(FHID/128, MM/128, 1),128,GEMM_SMEM>>>(
        h, ffn1_w, ffn1_b, 0, 0, ffnh, MM, FHID, CC, 0,0,0, 0.f);
    // 3) x_ffn = x + ffnh @ ffn2_w^T + b2
    gemm_tc<4,true,false,false><<<dim3(CC/128, MM/128, 1),128,GEMM_SMEM>>>(
        ffnh, ffn2_w, ffn2_b, x, 0, xffn, MM, CC, FHID, 0,0,0, 0.f);
    // 4) h = LN(x_ffn)
    ln_k<<<MM,256>>>(xffn, anorm_g, anorm_b, h);
    // 5) qkv = h @ qkv_w^T
    gemm_tc<0,true,false,false><<<dim3(3*CC/128, MM/128, 1),128,GEMM_SMEM>>>(
        h, qkv_w, 0, 0, 0, qkv, MM, 3*CC, CC, 0,0,0, 0.f);
    // 6) RoPE on q,k
    rope_k<<<(BB*TT*HH*32 + 255)/256, 256>>>(qkv, cosT, sinT);
    // 7) causal attention -> y
    attn_k<<<dim3(TT/64, HH, BB), 256, ATT_SMEM>>>(qkv, y);
    // 8) s = x_ffn + y @ proj_w^T + proj_b
    gemm_tc<4,true,false,false><<<dim3(CC/128, MM/128, 1),128,GEMM_SMEM>>>(
        y, proj_w, proj_b, xffn, 0, s, MM, CC, CC, 0,0,0, 0.f);
    // 9) mc = LN(s)
    ln_k<<<MM,256>>>(s, mnorm_g, mnorm_b, mc);
    // 10-13) cq/ck/cv/cg
    gemm_tc<2,true,false,false><<<dim3(CC/128, MM/128, 1),128,GEMM_SMEM>>>(
        mc, wq_w, wq_b, 0, 0, cq, MM, CC, CC, 0,0,0, 0.f);
    gemm_tc<1,true,false,false><<<dim3(CC/128, MM/128, 1),128,GEMM_SMEM>>>(
        mc, wk_w, wk_b, 0, 0, ck, MM, CC, CC, 0,0,0, 0.f);
    gemm_tc<1,true,false,false><<<dim3(CC/128, MM/128, 1),128,GEMM_SMEM>>>(
        mc, wv_w, wv_b, 0, 0, cv, MM, CC, CC, 0,0,0, 0.f);
    gemm_tc<3,true,false,false><<<dim3(CC/128, MM/128, 1),128,GEMM_SMEM>>>(
        mc, wg_w, wg_b, 0, 0, cg, MM, CC, CC, 0,0,0, 0.f);
    // 14) ck row-normalize
    knorm_k<<<MM,256>>>(ck);
    // 15) v_dyn = cg*(cv - (ck@mem)*scale)
    gemm_tc<5,false,false,false><<<dim3(CC/128, MM/128, 1),128,GEMM_SMEM>>>(
        ck, mem, 0, cv, cg, vdyn, MM, CC, CC, 0,0,0, MSCALE);
    // 16) mo = cq @ mem   (mo_prev, unscaled)
    gemm_tc<0,false,false,false><<<dim3(CC/128, MM/128, 1),128,GEMM_SMEM>>>(
        cq, mem, 0, 0, 0, mo, MM, CC, CC, 0,0,0, 0.f);
    // 17) sc_c = tril(cq @ ck^T)  (batched per b) -> second output
    gemm_tc<0,true,true,false><<<dim3(TT/128, TT/128, BB),128,GEMM_SMEM>>>(
        cq, ck, 0, 0, 0, out_sc, TT, TT, CC,
        (long)TT*CC, (long)TT*CC, (long)TT*TT, 0.f);
    // 18) mo = (mo_prev + sc_c @ v_dyn) * scale   (batched, triangular A)
    gemm_tc<6,false,false,true><<<dim3(CC/128, TT/128, BB),128,GEMM_SMEM>>>(
        out_sc, vdyn, 0, mo, 0, mo, TT, CC, TT,
        (long)TT*TT, (long)TT*CC, (long)TT*CC, MSCALE);
    // 19) woh = silu(mo @ wo_w^T + wo_b)
    gemm_tc<2,true,false,false><<<dim3(4*CC/128, MM/128, 1),128,GEMM_SMEM>>>(
        mo, wo_w, wo_b, 0, 0, woh, MM, 4*CC, CC, 0,0,0, 0.f);
    // 20) out = s + woh @ op_w^T + op_b
    gemm_tc<4,true,false,false><<<dim3(CC/128, MM/128, 1),128,GEMM_SMEM>>>(
        woh, op_w, op_b, s, 0, out, MM, CC, 4*CC, 0,0,0, 0.f);
}

// round 5
// speedup vs baseline: 2.9488x; 1.2352x over previous
#include <cuda_runtime.h>
#include <cuda_bf16.h>
#include <math.h>

// Problem constants
#define BB 2
#define TT 2048
#define CC 1024
#define HH 16
#define HD 64
#define FHID 1536
#define MM (BB*TT)          // 4096
#define MSCALE 0.03125f     // 1/sqrt(1024)

// ------------------------------------------------------------------
// Scratch (static device globals — no allocation allowed)
// ------------------------------------------------------------------
__device__ float g_h   [MM*CC];
__device__ float g_ffnh[MM*FHID];
__device__ float g_xffn[MM*CC];
__device__ float g_qkv [MM*3*CC];
__device__ float g_y   [MM*CC];
__device__ float g_s   [MM*CC];
__device__ float g_mc  [MM*CC];
__device__ float g_cq  [MM*CC];
__device__ float g_ck  [MM*CC];
__device__ float g_cv  [MM*CC];
__device__ float g_cg  [MM*CC];
__device__ float g_vdyn[MM*CC];
__device__ float g_mo  [MM*CC];
__device__ float g_woh [MM*4*CC];

__device__ __forceinline__ float sigm(float x){ return 1.f/(1.f+__expf(-x)); }

__device__ __forceinline__ void mma_tf32(float* c, const uint4& a, unsigned b0, unsigned b1)
{
    asm volatile(
        "mma.sync.aligned.m16n8k8.row.col.f32.tf32.tf32.f32 "
        "{%0,%1,%2,%3},{%4,%5,%6,%7},{%8,%9},{%0,%1,%2,%3};\n"
        : "+f"(c[0]), "+f"(c[1]), "+f"(c[2]), "+f"(c[3])
        : "r"(a.x), "r"(a.y), "r"(a.z), "r"(a.w), "r"(b0), "r"(b1));
}

__device__ __forceinline__ unsigned f2tf32(unsigned fbits)
{
    unsigned t;
    asm("cvt.rna.tf32.f32 %0, %1;" : "=r"(t) : "f"(__uint_as_float(fbits)));
    return t;
}

// ------------------------------------------------------------------
// LayerNorm
// ------------------------------------------------------------------
__global__ void __launch_bounds__(256) ln_k(const float* __restrict__ x,
                                            const float* __restrict__ g,
                                            const float* __restrict__ b,
                                            float* __restrict__ out)
{
    __shared__ float sa[8], sb[8];
    int row = blockIdx.x, tid = threadIdx.x;
    const float* xr = x + (long)row*CC;
    float4 v = *(const float4*)(xr + tid*4);
    float s = v.x+v.y+v.z+v.w;
    float q = v.x*v.x + v.y*v.y + v.z*v.z + v.w*v.w;
    int lane = tid & 31, wid = tid >> 5;
    #pragma unroll
    for (int o=16;o;o>>=1){ s += __shfl_down_sync(~0u,s,o); q += __shfl_down_sync(~0u,q,o); }
    if (lane==0){ sa[wid]=s; sb[wid]=q; }
    __syncthreads();
    if (tid==0){ float ss=0,qq=0; for(int i=0;i<8;i++){ss+=sa[i];qq+=sb[i];} sa[0]=ss; sb[0]=qq; }
    __syncthreads();
    float mean = sa[0]*(1.f/CC);
    float var  = sb[0]*(1.f/CC) - mean*mean;
    float rstd = rsqrtf(var + 1e-5f);
    float4 gv = *(const float4*)(g + tid*4);
    float4 bv = *(const float4*)(b + tid*4);
    float4 o;
    o.x = (v.x-mean)*rstd*gv.x + bv.x;
    o.y = (v.y-mean)*rstd*gv.y + bv.y;
    o.z = (v.z-mean)*rstd*gv.z + bv.z;
    o.w = (v.w-mean)*rstd*gv.w + bv.w;
    *(float4*)(out + (long)row*CC + tid*4) = o;
}

// ------------------------------------------------------------------
// Row L2-normalize in place (ck)
// ------------------------------------------------------------------
__global__ void __launch_bounds__(256) knorm_k(float* __restrict__ ck)
{
    __shared__ float sb[8];
    int row = blockIdx.x, tid = threadIdx.x;
    float* xr = ck + (long)row*CC;
    float4 v = *(const float4*)(xr + tid*4);
    float q = v.x*v.x + v.y*v.y + v.z*v.z + v.w*v.w;
    int lane = tid & 31, wid = tid >> 5;
    #pragma unroll
    for (int o=16;o;o>>=1) q += __shfl_down_sync(~0u,q,o);
    if (lane==0) sb[wid]=q;
    __syncthreads();
    if (tid==0){ float qq=0; for(int i=0;i<8;i++) qq+=sb[i]; sb[0]=qq; }
    __syncthreads();
    float inv = 1.f / fmaxf(sqrtf(sb[0]), 1e-5f);
    v.x*=inv; v.y*=inv; v.z*=inv; v.w*=inv;
    *(float4*)(xr + tid*4) = v;
}

// ------------------------------------------------------------------
// RoPE on q and k inside qkv buffer (in-place)
// ------------------------------------------------------------------
__global__ void __launch_bounds__(256) rope_k(float* __restrict__ qkv,
                                              const float* __restrict__ cosT,
                                              const float* __restrict__ sinT)
{
    int idx = blockIdx.x*blockDim.x + threadIdx.x;
    if (idx >= BB*TT*HH*32) return;
    int d = idx & 31;
    int h = (idx >> 5) & 15;
    int t = (idx >> 9) & (TT-1);
    int b = idx >> 20;
    float c0 = cosT[t*HD + d],    s0 = sinT[t*HD + d];
    float c1 = cosT[t*HD + d+32], s1 = sinT[t*HD + d+32];
    long base = ((long)(b*TT + t))*3*CC + h*HD;
    float q0 = qkv[base + d], q1 = qkv[base + d + 32];
    qkv[base + d]      = q0*c0 - q1*s0;
    qkv[base + d + 32] = q1*c1 + q0*s1;
    base += CC;
    float k0 = qkv[base + d], k1 = qkv[base + d + 32];
    qkv[base + d]      = k0*c0 - k1*s0;
    qkv[base + d + 32] = k1*c1 + k0*s1;
}

// ==================================================================
// Tensor-core tf32 causal flash attention.
// CTA = 64 q-rows of one (b,h). 128 threads = 4 warps, warp = m16.
// Fragment-packed smem layouts identical in structure to gemm_tc.
// ==================================================================
#define ATT2_SMEM (16896*4)   // Qf,Kf,Vf 4224 u32 each + Pf 4224 u32

__global__ void __launch_bounds__(128) attn_tc(const float* __restrict__ qkv,
                                               float* __restrict__ y)
{
    extern __shared__ unsigned su[];
    unsigned* Qf = su;
    unsigned* Kf = su + 4224;
    unsigned* Vf = su + 8448;
    unsigned* Pf = su + 12672;

    int tid  = threadIdx.x;
    int lane = tid & 31, w = tid >> 5;
    int g    = lane >> 2, tig = lane & 3;
    int qt   = (int)(gridDim.x - 1) - (int)blockIdx.x;   // long tiles first
    int hh   = blockIdx.y, b = blockIdx.z;
    long base = ((long)b*TT)*3*CC + hh*HD;

    int up4 = (lane ^ (lane>>3))*4;

    // ---- load + frag-pack Q (scaled by 1/sqrt(HD)) ----
    #pragma unroll
    for (int i=0;i<8;i++){
        int m  = (tid>>4) + i*8;
        int d0 = (tid&15)*4;
        float4 v = *(const float4*)(qkv + base + (long)(qt*64+m)*3*CC + d0);
        float vv[4] = {v.x*0.125f, v.y*0.125f, v.z*0.125f, v.w*0.125f};
        #pragma unroll
        for (int j=0;j<4;j++){
            int d  = d0 + j;
            int row = (d>>3)*4 + (m>>4);
            int ul  = (m&7)*4 + (d&3);
            int up  = ul ^ (ul>>3);
            int r   = ((m>>3)&1) + 2*((d>>2)&1);
            Qf[row*132 + up*4 + r] = f2tf32(__float_as_uint(vv[j]));
        }
    }

    float m_run[2] = {-1e30f, -1e30f};
    float l_run[2] = {0.f, 0.f};
    float acc_o[4][2][4];
    #pragma unroll
    for (int p=0;p<4;p++) for (int sb=0;sb<2;sb++) for (int e=0;e<4;e++)
        acc_o[p][sb][e] = 0.f;

    uint4 rk[8], rv[8];
    auto ldkv = [&](int jt){
        #pragma unroll
        for (int i=0;i<8;i++){
            int kv = (tid>>4) + i*8;
            int d0 = (tid&15)*4;
            long rb = base + (long)(jt*64+kv)*3*CC + d0;
            rk[i] = *(const uint4*)(qkv + rb + CC);
            rv[i] = *(const uint4*)(qkv + rb + 2*CC);
        }
    };
    ldkv(0);

    for (int jt=0; jt<=qt; jt++){
        // ---- STS K,V frags ----
        #pragma unroll
        for (int i=0;i<8;i++){
            int kv = (tid>>4) + i*8;
            int d0 = (tid&15)*4;
            unsigned kvals[4] = {rk[i].x, rk[i].y, rk[i].z, rk[i].w};
            unsigned vvals[4] = {rv[i].x, rv[i].y, rv[i].z, rv[i].w};
            #pragma unroll
            for (int j=0;j<4;j++){
                int d = d0 + j;
                {   // K: B-frag (n=kv, k=d)
                    int row = (d>>3)*4 + (kv>>4);
                    int ul  = (kv&7)*4 + (d&3);
                    int up  = ul ^ (ul>>3);
                    int r   = ((d>>2)&1) + 2*((kv>>3)&1);
                    Kf[row*132 + up*4 + r] = f2tf32(kvals[j]);
                }
                {   // V: B-frag (n=d, k=kv)
                    int row = (kv>>3)*4 + (d>>4);
                    int ul  = (d&7)*4 + (kv&3);
                    int up  = ul ^ (ul>>3);
                    int r   = ((kv>>2)&1) + 2*((d>>3)&1);
                    Vf[row*132 + up*4 + r] = f2tf32(vvals[j]);
                }
            }
        }
        __syncthreads();
        if (jt+1 <= qt) ldkv(jt+1);

        // ---- S = Q K^T ----
        float s[4][2][4];
        #pragma unroll
        for (int p=0;p<4;p++) for (int sb=0;sb<2;sb++) for (int e=0;e<4;e++)
            s[p][sb][e] = 0.f;
        #pragma unroll
        for (int kc=0;kc<8;kc++){
            uint4 af = *(const uint4*)&Qf[(kc*4 + w)*132 + up4];
            #pragma unroll
            for (int nb=0;nb<4;nb++){
                uint4 bf = *(const uint4*)&Kf[(kc*4 + nb)*132 + up4];
                mma_tf32(s[nb][0], af, bf.x, bf.y);
                mma_tf32(s[nb][1], af, bf.z, bf.w);
            }
        }

        // ---- causal mask on diagonal tile ----
        if (jt == qt){
            #pragma unroll
            for (int p=0;p<4;p++)
            #pragma unroll
            for (int sb=0;sb<2;sb++)
            #pragma unroll
            for (int e=0;e<4;e++){
                int col  = p*16 + sb*8 + tig*2 + (e&1);
                int rowl = w*16 + g + (e>>1)*8;
                if (col > rowl) s[p][sb][e] = -1e30f;
            }
        }

        // ---- online softmax (per half: rows g and g+8) ----
        float alpha[2];
        #pragma unroll
        for (int h2=0; h2<2; h2++){
            float mx = -1e30f;
            #pragma unroll
            for (int p=0;p<4;p++)
            #pragma unroll
            for (int sb=0;sb<2;sb++)
            #pragma unroll
            for (int j=0;j<2;j++)
                mx = fmaxf(mx, s[p][sb][h2*2+j]);
            mx = fmaxf(mx, __shfl_xor_sync(~0u, mx, 1));
            mx = fmaxf(mx, __shfl_xor_sync(~0u, mx, 2));
            float mnew = fmaxf(m_run[h2], mx);
            alpha[h2]  = __expf(m_run[h2] - mnew);
            m_run[h2]  = mnew;
            float sum = 0.f;
            #pragma unroll
            for (int p=0;p<4;p++)
            #pragma unroll
            for (int sb=0;sb<2;sb++)
            #pragma unroll
            for (int j=0;j<2;j++){
                float pv = __expf(s[p][sb][h2*2+j] - mnew);
                s[p][sb][h2*2+j] = pv;
                sum += pv;
            }
            sum += __shfl_xor_sync(~0u, sum, 1);
            sum += __shfl_xor_sync(~0u, sum, 2);
            l_run[h2] = l_run[h2]*alpha[h2] + sum;
        }
        #pragma unroll
        for (int p=0;p<4;p++)
        #pragma unroll
        for (int sb=0;sb<2;sb++)
        #pragma unroll
        for (int e=0;e<4;e++)
            acc_o[p][sb][e] *= alpha[e>>1];

        // ---- repack P into A-frags (per-warp private region) ----
        unsigned* pw = Pf + w*1056;
        #pragma unroll
        for (int p=0;p<4;p++)
        #pragma unroll
        for (int sb=0;sb<2;sb++)
        #pragma unroll
        for (int e=0;e<4;e++){
            int col = p*16 + sb*8 + tig*2 + (e&1);
            int m   = g + (e>>1)*8;
            int ul  = (m&7)*4 + (col&3);
            int up  = ul ^ (ul>>3);
            int r   = ((m>>3)&1) + 2*((col>>2)&1);
            pw[(col>>3)*132 + up*4 + r] = f2tf32(__float_as_uint(s[p][sb][e]));
        }
        __syncwarp();

        // ---- O += P V ----
        #pragma unroll
        for (int kc=0;kc<8;kc++){
            uint4 af = *(const uint4*)&pw[kc*132 + up4];
            #pragma unroll
            for (int nb=0;nb<4;nb++){
                uint4 bf = *(const uint4*)&Vf[(kc*4 + nb)*132 + up4];
                mma_tf32(acc_o[nb][0], af, bf.x, bf.y);
                mma_tf32(acc_o[nb][1], af, bf.z, bf.w);
            }
        }
        __syncthreads();   // protect Kf/Vf (+ per-warp Pf) before next overwrite
    }

    // ---- normalize + write y [B,T,C] ----
    float inv0 = 1.f/l_run[0], inv1 = 1.f/l_run[1];
    #pragma unroll
    for (int p=0;p<4;p++)
    #pragma unroll
    for (int sb=0;sb<2;sb++)
    #pragma unroll
    for (int h2=0;h2<2;h2++){
        int col = p*16 + sb*8 + tig*2;
        int t   = qt*64 + w*16 + g + h2*8;
        long off = ((long)b*TT + t)*CC + hh*HD + col;
        float iv = h2 ? inv1 : inv0;
        *(float2*)(y + off) = make_float2(acc_o[p][sb][h2*2]*iv, acc_o[p][sb][h2*2+1]*iv);
    }
}

// ==================================================================
// TF32 tensor-core GEMM (single-barrier pipeline).
// ==================================================================
#define GEMM_SMEM (4*4224*4)

template<int EPI, bool TRANSB, bool CAUSAL, bool TRIA>
__global__ void __launch_bounds__(128) gemm_tc(
    const float* __restrict__ A, const float* __restrict__ Bm,
    const float* __restrict__ bias, const float* __restrict__ ep0,
    const float* __restrict__ ep1, float* __restrict__ C,
    int M, int N, int K, long sA, long sB, long sC, float scale)
{
    constexpr int BM=128, BK=32;
    int m0 = blockIdx.y*BM, n0 = blockIdx.x*128;
    long z = blockIdx.z;
    A  += z*sA;  Bm += z*sB;  C += z*sC;
    const float* e0 = ep0 ? ep0 + z*sC : (const float*)0;
    const float* e1 = ep1 ? ep1 + z*sC : (const float*)0;

    int tid  = threadIdx.x;
    int lane = tid & 31;
    int wid  = tid >> 5;
    int wm   = wid >> 1, wn = wid & 1;
    int g    = lane >> 2, tig = lane & 3;

    if (CAUSAL && n0 > m0 + BM - 1){
        #pragma unroll
        for (int mt=0;mt<4;mt++)
        #pragma unroll
        for (int p=0;p<4;p++)
        #pragma unroll
        for (int sub=0;sub<2;sub++){
            int col = n0 + wn*64 + p*16 + sub*8 + tig*2;
            #pragma unroll
            for (int half=0;half<2;half++){
                int row = m0 + wm*64 + mt*16 + g + half*8;
                *(float2*)(C + (long)row*N + col) = make_float2(0.f,0.f);
            }
        }
        return;
    }

    extern __shared__ unsigned smem_u[];
    unsigned* Abuf[2] = { smem_u,          smem_u + 4224 };
    unsigned* Bbuf[2] = { smem_u + 8448,   smem_u + 12672 };

    float acc[4][4][2][4];
    #pragma unroll
    for (int a=0;a<4;a++) for (int b=0;b<4;b++) for (int c=0;c<2;c++) for (int d=0;d<4;d++)
        acc[a][b][c][d] = 0.f;

    int kmax = TRIA ? min(K, m0 + BM) : K;
    int nchunks = kmax / BK;

    uint4 ra[8], rb[8];

    auto ldgA = [&](int c){
        long kb = (long)c*BK;
        #pragma unroll
        for (int i=0;i<8;i++){
            int m = (tid>>3) + i*16;
            ra[i] = *(const uint4*)(A + (long)(m0+m)*K + kb + (tid&7)*4);
        }
    };
    auto ldgB = [&](int c){
        long kb = (long)c*BK;
        if (TRANSB){
            #pragma unroll
            for (int i=0;i<8;i++){
                int n = (tid>>3) + i*16;
                rb[i] = *(const uint4*)(Bm + (long)(n0+n)*K + kb + (tid&7)*4);
            }
        } else {
            #pragma unroll
            for (int i=0;i<8;i++){
                int k = (tid>>5) + i*4;
                rb[i] = *(const uint4*)(Bm + (kb + k)*(long)N + n0 + (tid&31)*4);
            }
        }
    };

    auto stsA = [&](int buf){
        unsigned* dst = Abuf[buf];
        #pragma unroll
        for (int i=0;i<8;i++){
            int m  = (tid>>3) + i*16;
            int kk = (tid&7)*4;
            unsigned vals[4] = { ra[i].x, ra[i].y, ra[i].z, ra[i].w };
            #pragma unroll
            for (int j=0;j<4;j++){
                int kl = kk + j;
                int ul = (m&7)*4 + j;
                int up = ul ^ (ul>>3);
                int r  = ((m>>3)&1) + 2*((kl>>2)&1);
                dst[((kl>>3)*8 + (m>>4))*132 + up*4 + r] = f2tf32(vals[j]);
            }
        }
    };
    auto stsB = [&](int buf){
        unsigned* dst = Bbuf[buf];
        if (TRANSB){
            #pragma unroll
            for (int i=0;i<8;i++){
                int n  = (tid>>3) + i*16;
                int kk = (tid&7)*4;
                unsigned vals[4] = { rb[i].x, rb[i].y, rb[i].z, rb[i].w };
                #pragma unroll
                for (int j=0;j<4;j++){
                    int kl = kk + j;
                    int ul = (n&7)*4 + (kl&3);
                    int up = ul ^ (ul>>3);
                    int r  = ((kl>>2)&1) + 2*((n>>3)&1);
                    dst[((kl>>3)*8 + (n>>4))*132 + up*4 + r] = f2tf32(vals[j]);
                }
            }
        } else {
            #pragma unroll
            for (int i=0;i<8;i++){
                int k  = (tid>>5) + i*4;
                int nn = (tid&31)*4;
                unsigned vals[4] = { rb[i].x, rb[i].y, rb[i].z, rb[i].w };
                #pragma unroll
                for (int j=0;j<4;j++){
                    int n  = nn + j;
                    int ul = (n&7)*4 + (k&3);
                    int up = ul ^ (ul>>3);
                    int r  = ((k>>2)&1) + 2*((n>>3)&1);
                    dst[((k>>3)*8 + (n>>4))*132 + up*4 + r] = f2tf32(vals[j]);
                }
            }
        }
    };

    int up4 = (lane ^ (lane>>3))*4;

    auto compute = [&](int buf){
        const unsigned* As = Abuf[buf];
        const unsigned* Bs = Bbuf[buf];
        #pragma unroll
        for (int ks=0;ks<4;ks++){
            uint4 af[4], bf[4];
            #pragma unroll
            for (int mt=0;mt<4;mt++)
                af[mt] = *(const uint4*)&As[(ks*8 + wm*4 + mt)*132 + up4];
            #pragma unroll
            for (int p=0;p<4;p++)
                bf[p] = *(const uint4*)&Bs[(ks*8 + wn*4 + p)*132 + up4];
            #pragma unroll
            for (int mt=0;mt<4;mt++)
                #pragma unroll
                for (int p=0;p<4;p++){
                    mma_tf32(acc[mt][p][0], af[mt], bf[p].x, bf[p].y);
                    mma_tf32(acc[mt][p][1], af[mt], bf[p].z, bf[p].w);
                }
        }
    };

    // ---- pipeline (one barrier per chunk) ----
    ldgA(0); ldgB(0);
    stsA(0); stsB(0);
    __syncthreads();
    for (int c=0;c<nchunks;c++){
        if (c+1 < nchunks){ ldgA(c+1); ldgB(c+1); }
        compute(c&1);
        if (c+1 < nchunks){
            stsA((c+1)&1); stsB((c+1)&1);
            __syncthreads();
        }
    }

    // ---- epilogue ----
    #pragma unroll
    for (int mt=0;mt<4;mt++)
    #pragma unroll
    for (int p=0;p<4;p++)
    #pragma unroll
    for (int sub=0;sub<2;sub++){
        int col = n0 + wn*64 + p*16 + sub*8 + tig*2;
        float2 bv = make_float2(0.f,0.f);
        if (EPI>=1 && EPI<=4) bv = *(const float2*)(bias + col);
        #pragma unroll
        for (int half=0;half<2;half++){
            int row = m0 + wm*64 + mt*16 + g + half*8;
            long idx = (long)row*N + col;
            float v0 = acc[mt][p][sub][half*2+0];
            float v1 = acc[mt][p][sub][half*2+1];
            if (EPI==1){ v0 += bv.x; v1 += bv.y; }
            else if (EPI==2){ v0 += bv.x; v1 += bv.y; v0 = v0*sigm(v0); v1 = v1*sigm(v1); }
            else if (EPI==3){ v0 = sigm(v0+bv.x); v1 = sigm(v1+bv.y); }
            else if (EPI==4){ float2 e = *(const float2*)(e0+idx); v0 += bv.x + e.x; v1 += bv.y + e.y; }
            else if (EPI==5){ float2 a = *(const float2*)(e0+idx); float2 gg = *(const float2*)(e1+idx);
                              v0 = gg.x*(a.x - v0*scale); v1 = gg.y*(a.y - v1*scale); }
            else if (EPI==6){ float2 a = *(const float2*)(e0+idx);
                              v0 = (a.x + v0)*scale; v1 = (a.y + v1)*scale; }
            if (CAUSAL){
                if (col   > row) v0 = 0.f;
                if (col+1 > row) v1 = 0.f;
            }
            *(float2*)(C + idx) = make_float2(v0, v1);
        }
    }
}

// ------------------------------------------------------------------
// Launcher
// ------------------------------------------------------------------
static float *p_h, *p_ffnh, *p_xffn, *p_qkv, *p_y, *p_s, *p_mc, *p_cq,
             *p_ck, *p_cv, *p_cg, *p_vdyn, *p_mo, *p_woh;
static bool  s_init = false;

extern "C" void kernel_launch(void* const* d_in, const int* in_sizes, int n_in,
                              void* d_out, int out_size)
{
    (void)in_sizes; (void)n_in; (void)out_size;
    const float* x      = (const float*)d_in[0];
    const float* cosT   = (const float*)d_in[1];
    const float* sinT   = (const float*)d_in[2];
    const float* qkv_w  = (const float*)d_in[3];
    const float* proj_w = (const float*)d_in[4];
    const float* proj_b = (const float*)d_in[5];
    const float* norm_g = (const float*)d_in[6];
    const float* norm_b = (const float*)d_in[7];
    const float* anorm_g= (const float*)d_in[8];
    const float* anorm_b= (const float*)d_in[9];
    const float* ffn1_w = (const float*)d_in[10];
    const float* ffn1_b = (const float*)d_in[11];
    const float* ffn2_w = (const float*)d_in[12];
    const float* ffn2_b = (const float*)d_in[13];
    const float* mem    = (const float*)d_in[14];
    const float* mnorm_g= (const float*)d_in[17];
    const float* mnorm_b= (const float*)d_in[18];
    const float* wq_w   = (const float*)d_in[19];
    const float* wq_b   = (const float*)d_in[20];
    const float* wk_w   = (const float*)d_in[21];
    const float* wk_b   = (const float*)d_in[22];
    const float* wv_w   = (const float*)d_in[23];
    const float* wv_b   = (const float*)d_in[24];
    const float* wg_w   = (const float*)d_in[25];
    const float* wg_b   = (const float*)d_in[26];
    const float* wo_w   = (const float*)d_in[27];
    const float* wo_b   = (const float*)d_in[28];
    const float* op_w   = (const float*)d_in[29];
    const float* op_b   = (const float*)d_in[30];

    if (!s_init){
        cudaGetSymbolAddress((void**)&p_h,    g_h);
        cudaGetSymbolAddress((void**)&p_ffnh, g_ffnh);
        cudaGetSymbolAddress((void**)&p_xffn, g_xffn);
        cudaGetSymbolAddress((void**)&p_qkv,  g_qkv);
        cudaGetSymbolAddress((void**)&p_y,    g_y);
        cudaGetSymbolAddress((void**)&p_s,    g_s);
        cudaGetSymbolAddress((void**)&p_mc,   g_mc);
        cudaGetSymbolAddress((void**)&p_cq,   g_cq);
        cudaGetSymbolAddress((void**)&p_ck,   g_ck);
        cudaGetSymbolAddress((void**)&p_cv,   g_cv);
        cudaGetSymbolAddress((void**)&p_cg,   g_cg);
        cudaGetSymbolAddress((void**)&p_vdyn, g_vdyn);
        cudaGetSymbolAddress((void**)&p_mo,   g_mo);
        cudaGetSymbolAddress((void**)&p_woh,  g_woh);
        cudaFuncSetAttribute(attn_tc, cudaFuncAttributeMaxDynamicSharedMemorySize, ATT2_SMEM);
        {
            auto* f0 = gemm_tc<0,true ,false,false>;
            auto* f1 = gemm_tc<1,true ,false,false>;
            auto* f2 = gemm_tc<2,true ,false,false>;
            auto* f3 = gemm_tc<3,true ,false,false>;
            auto* f4 = gemm_tc<4,true ,false,false>;
            auto* f5 = gemm_tc<5,false,false,false>;
            auto* f6 = gemm_tc<0,false,false,false>;
            auto* f7 = gemm_tc<0,true ,true ,false>;
            auto* f8 = gemm_tc<6,false,false,true >;
            cudaFuncSetAttribute(f0, cudaFuncAttributeMaxDynamicSharedMemorySize, GEMM_SMEM);
            cudaFuncSetAttribute(f1, cudaFuncAttributeMaxDynamicSharedMemorySize, GEMM_SMEM);
            cudaFuncSetAttribute(f2, cudaFuncAttributeMaxDynamicSharedMemorySize, GEMM_SMEM);
            cudaFuncSetAttribute(f3, cudaFuncAttributeMaxDynamicSharedMemorySize, GEMM_SMEM);
            cudaFuncSetAttribute(f4, cudaFuncAttributeMaxDynamicSharedMemorySize, GEMM_SMEM);
            cudaFuncSetAttribute(f5, cudaFuncAttributeMaxDynamicSharedMemorySize, GEMM_SMEM);
            cudaFuncSetAttribute(f6, cudaFuncAttributeMaxDynamicSharedMemorySize, GEMM_SMEM);
            cudaFuncSetAttribute(f7, cudaFuncAttributeMaxDynamicSharedMemorySize, GEMM_SMEM);
            cudaFuncSetAttribute(f8, cudaFuncAttributeMaxDynamicSharedMemorySize, GEMM_SMEM);
        }
        s_init = true;
    }
    float *h=p_h, *ffnh=p_ffnh, *xffn=p_xffn, *qkv=p_qkv, *y=p_y, *s=p_s,
          *mc=p_mc, *cq=p_cq, *ck=p_ck, *cv=p_cv, *cg=p_cg, *vdyn=p_vdyn,
          *mo=p_mo, *woh=p_woh;

    float* out    = (float*)d_out;
    float* out_sc = out + (long)MM*CC;

    // 1) h = LN(x)
    ln_k<<<MM,256>>>(x, norm_g, norm_b, h);
    // 2) ffnh = silu(h @ ffn1_w^T + b1)
    gemm_tc<2,true,false,false><<<dim3(FHID/128, MM/128, 1),128,GEMM_SMEM>>>(
        h, ffn1_w, ffn1_b, 0, 0, ffnh, MM, FHID, CC, 0,0,0, 0.f);
    // 3) x_ffn = x + ffnh @ ffn2_w^T + b2
    gemm_tc<4,true,false,false><<<dim3(CC/128, MM/128, 1),128,GEMM_SMEM>>>(
        ffnh, ffn2_w, ffn2_b, x, 0, xffn, MM, CC, FHID, 0,0,0, 0.f);
    // 4) h = LN(x_ffn)
    ln_k<<<MM,256>>>(xffn, anorm_g, anorm_b, h);
    // 5) qkv = h @ qkv_w^T
    gemm_tc<0,true,false,false><<<dim3(3*CC/128, MM/128, 1),128,GEMM_SMEM>>>(
        h, qkv_w, 0, 0, 0, qkv, MM, 3*CC, CC, 0,0,0, 0.f);
    // 6) RoPE on q,k
    rope_k<<<(BB*TT*HH*32 + 255)/256, 256>>>(qkv, cosT, sinT);
    // 7) causal attention -> y (tensor cores)
    attn_tc<<<dim3(TT/64, HH, BB), 128, ATT2_SMEM>>>(qkv, y);
    // 8) s = x_ffn + y @ proj_w^T + proj_b
    gemm_tc<4,true,false,false><<<dim3(CC/128, MM/128, 1),128,GEMM_SMEM>>>(
        y, proj_w, proj_b, xffn, 0, s, MM, CC, CC, 0,0,0, 0.f);
    // 9) mc = LN(s)
    ln_k<<<MM,256>>>(s, mnorm_g, mnorm_b, mc);
    // 10-13) cq/ck/cv/cg
    gemm_tc<2,true,false,false><<<dim3(CC/128, MM/128, 1),128,GEMM_SMEM>>>(
        mc, wq_w, wq_b, 0, 0, cq, MM, CC, CC, 0,0,0, 0.f);
    gemm_tc<1,true,false,false><<<dim3(CC/128, MM/128, 1),128,GEMM_SMEM>>>(
        mc, wk_w, wk_b, 0, 0, ck, MM, CC, CC, 0,0,0, 0.f);
    gemm_tc<1,true,false,false><<<dim3(CC/128, MM/128, 1),128,GEMM_SMEM>>>(
        mc, wv_w, wv_b, 0, 0, cv, MM, CC, CC, 0,0,0, 0.f);
    gemm_tc<3,true,false,false><<<dim3(CC/128, MM/128, 1),128,GEMM_SMEM>>>(
        mc, wg_w, wg_b, 0, 0, cg, MM, CC, CC, 0,0,0, 0.f);
    // 14) ck row-normalize
    knorm_k<<<MM,256>>>(ck);
    // 15) v_dyn = cg*(cv - (ck@mem)*scale)
    gemm_tc<5,false,false,false><<<dim3(CC/128, MM/128, 1),128,GEMM_SMEM>>>(
        ck, mem, 0, cv, cg, vdyn, MM, CC, CC, 0,0,0, MSCALE);
    // 16) mo = cq @ mem   (mo_prev, unscaled)
    gemm_tc<0,false,false,false><<<dim3(CC/128, MM/128, 1),128,GEMM_SMEM>>>(
        cq, mem, 0, 0, 0, mo, MM, CC, CC, 0,0,0, 0.f);
    // 17) sc_c = tril(cq @ ck^T)  (batched per b) -> second output
    gemm_tc<0,true,true,false><<<dim3(TT/128, TT/128, BB),128,GEMM_SMEM>>>(
        cq, ck, 0, 0, 0, out_sc, TT, TT, CC,
        (long)TT*CC, (long)TT*CC, (long)TT*TT, 0.f);
    // 18) mo = (mo_prev + sc_c @ v_dyn) * scale   (batched, triangular A)
    gemm_tc<6,false,false,true><<<dim3(CC/128, TT/128, BB),128,GEMM_SMEM>>>(
        out_sc, vdyn, 0, mo, 0, mo, TT, CC, TT,
        (long)TT*TT, (long)TT*CC, (long)TT*CC, MSCALE);
    // 19) woh = silu(mo @ wo_w^T + wo_b)
    gemm_tc<2,true,false,false><<<dim3(4*CC/128, MM/128, 1),128,GEMM_SMEM>>>(
        mo, wo_w, wo_b, 0, 0, woh, MM, 4*CC, CC, 0,0,0, 0.f);
    // 20) out = s + woh @ op_w^T + op_b
    gemm_tc<4,true,false,false><<<dim3(CC/128, MM/128, 1),128,GEMM_SMEM>>>(
        woh, op_w, op_b, s, 0, out, MM, CC, 4*CC, 0,0,0, 0.f);
}